// round 6
// baseline (speedup 1.0000x reference)
#include <cuda_runtime.h>
#include <cuda_bf16.h>
#include <mma.h>
#include <math.h>

using namespace nvcuda;

#define N_NODES 100000
#define N_EDGES 1000000

// Scratch (device globals — no dynamic allocation allowed)
__device__ __align__(16) float g_dinv[N_NODES];               // deg -> dinv (in place)
__device__ __align__(16) float g_xw[(size_t)N_NODES * 128];   // [:,0:64]=user xw, [:,64:128]=movie xw
__device__ __align__(16) float g_agg[(size_t)N_NODES * 128];  // aggregated output of both convs

// ---------------------------------------------------------------------------
// K0: init degree with self-loop weight 1
__global__ void k_deg_init() {
    int i = blockIdx.x * blockDim.x + threadIdx.x;
    if (i < N_NODES) g_dinv[i] = 1.0f;
}

// K1: accumulate edge weights into degree at col (edge_index is int32)
__global__ void k_deg_accum(const int* __restrict__ ei, const float* __restrict__ ew) {
    int e = blockIdx.x * blockDim.x + threadIdx.x;
    if (e < N_EDGES) {
        int col = ei[N_EDGES + e];
        atomicAdd(&g_dinv[col], ew[e]);
    }
}

// K2: deg -> rsqrt(deg)
__global__ void k_dinv() {
    int i = blockIdx.x * blockDim.x + threadIdx.x;
    if (i < N_NODES) {
        float d = g_dinv[i];
        g_dinv[i] = (d > 0.0f) ? rsqrtf(d) : 0.0f;
    }
}

// K3: xw = x@W (both convs) + agg init with self-loop term + bias.
// 8 nodes per 128-thread block; features staged coalesced; W in registers.
__global__ void __launch_bounds__(128) k_xw(
    const float* __restrict__ user_x, const float* __restrict__ movie_x,
    const float* __restrict__ Wu, const float* __restrict__ bu,
    const float* __restrict__ Wm, const float* __restrict__ bm)
{
    int nb = blockIdx.x * 8;     // first node of this block
    int j  = threadIdx.x;        // 0..127 output channel
    __shared__ float su[8 * 3];
    __shared__ float sv[8 * 18];

    if (j < 24) su[j] = user_x[(size_t)nb * 3 + j];
    for (int i = j; i < 144; i += 128) sv[i] = movie_x[(size_t)nb * 18 + i];

    float w[18], bias;
    if (j < 64) {
        #pragma unroll
        for (int k = 0; k < 3; k++) w[k] = Wu[k * 64 + j];
        bias = bu[j];
    } else {
        int jj = j - 64;
        #pragma unroll
        for (int k = 0; k < 18; k++) w[k] = Wm[k * 64 + jj];
        bias = bm[jj];
    }
    __syncthreads();

    #pragma unroll
    for (int nd = 0; nd < 8; nd++) {
        int n = nb + nd;
        float acc = 0.0f;
        if (j < 64) {
            #pragma unroll
            for (int k = 0; k < 3; k++) acc = fmaf(su[nd * 3 + k], w[k], acc);
        } else {
            #pragma unroll
            for (int k = 0; k < 18; k++) acc = fmaf(sv[nd * 18 + k], w[k], acc);
        }
        float dv = g_dinv[n];
        size_t o = (size_t)n * 128 + j;
        g_xw[o]  = acc;
        g_agg[o] = dv * dv * acc + bias;
    }
}

// K4: scatter-aggregate. One warp per edge; float4 gather + red.global.add.v4.
__global__ void __launch_bounds__(256) k_scatter(
    const int* __restrict__ ei, const float* __restrict__ ew)
{
    int gw = (blockIdx.x * blockDim.x + threadIdx.x) >> 5;
    int lane = threadIdx.x & 31;
    if (gw >= N_EDGES) return;

    int row = ei[gw];
    int col = ei[N_EDGES + gw];
    float norm = g_dinv[row] * ew[gw] * g_dinv[col];

    const float4* src = reinterpret_cast<const float4*>(g_xw + (size_t)row * 128) + lane;
    float4 v = *src;
    v.x *= norm; v.y *= norm; v.z *= norm; v.w *= norm;

    float* dst = g_agg + (size_t)col * 128 + lane * 4;
    asm volatile("red.global.add.v4.f32 [%0], {%1, %2, %3, %4};"
                 :: "l"(dst), "f"(v.x), "f"(v.y), "f"(v.z), "f"(v.w)
                 : "memory");
}

// ---------------------------------------------------------------------------
// K5: MLP head via tensor cores, 3xTF32 for ~fp32 accuracy.
//   h = relu(agg @ W1 + b1);  out = h @ W2 + b2
// Block: 256 threads (8 warps). Node tile = 16 (6250 tiles, grid 625 x 10).
// Each warp owns one 16-wide channel tile (8 warps x 16 = 128 channels).
// Dynamic smem: W1 fp32 (64KB, staged once/block) + A tile + H tile.

#define MLP_BLOCKS 625
#define TILES_PER_BLOCK 10       // 625 * 10 * 16 = 100000
#define A_LD 132                  // 128 + 4 pad

extern __shared__ float s_mlp[];  // layout: Bs[128*128] | As[16*A_LD] | Hs[16*128]

__global__ void __launch_bounds__(256) k_mlp(
    const float* __restrict__ W1, const float* __restrict__ b1,
    const float* __restrict__ W2, const float* __restrict__ b2,
    float* __restrict__ out)
{
    float* Bs = s_mlp;                    // [128][128] row-major (k, n)
    float* As = Bs + 128 * 128;           // [16][A_LD]  (node, k)
    float* Hs = As + 16 * A_LD;           // [16][128]

    int tid  = threadIdx.x;
    int wid  = tid >> 5;                  // 0..7 => channel tile
    int lane = tid & 31;

    // Stage W1 once per block (row-major k x n, same as input layout)
    for (int i = tid; i < 128 * 128; i += 256) Bs[i] = W1[i];
    __syncthreads();

    for (int t = 0; t < TILES_PER_BLOCK; t++) {
        int tile = blockIdx.x * TILES_PER_BLOCK + t;
        int n0 = tile * 16;

        // Stage A: 16 nodes x 128 feats, coalesced
        for (int i = tid; i < 16 * 128; i += 256) {
            int r = i >> 7, c = i & 127;
            As[r * A_LD + c] = g_agg[(size_t)(n0 + r) * 128 + c];
        }
        __syncthreads();

        // GEMM: 16x16 output tile per warp, K=128 in steps of 8, 3xTF32
        wmma::fragment<wmma::accumulator, 16, 16, 8, float> acc;
        wmma::fill_fragment(acc, 0.0f);

        #pragma unroll
        for (int k0 = 0; k0 < 128; k0 += 8) {
            wmma::fragment<wmma::matrix_a, 16, 16, 8, wmma::precision::tf32, wmma::row_major> a, alo;
            wmma::fragment<wmma::matrix_b, 16, 16, 8, wmma::precision::tf32, wmma::row_major> b, blo;
            wmma::load_matrix_sync(a, As + k0, A_LD);
            wmma::load_matrix_sync(b, Bs + k0 * 128 + wid * 16, 128);
            #pragma unroll
            for (int i = 0; i < a.num_elements; i++) {
                float x = a.x[i];
                float hi = wmma::__float_to_tf32(x);
                a.x[i]   = hi;
                alo.x[i] = wmma::__float_to_tf32(x - hi);
            }
            #pragma unroll
            for (int i = 0; i < b.num_elements; i++) {
                float x = b.x[i];
                float hi = wmma::__float_to_tf32(x);
                b.x[i]   = hi;
                blo.x[i] = wmma::__float_to_tf32(x - hi);
            }
            wmma::mma_sync(acc, a,   blo, acc);
            wmma::mma_sync(acc, alo, b,   acc);
            wmma::mma_sync(acc, a,   b,   acc);
        }
        wmma::store_matrix_sync(Hs + wid * 16, acc, 128, wmma::mem_row_major);
        __syncthreads();

        // Epilogue: out[n] = sum_c relu(H[n][c] + b1[c]) * W2[c] + b2
        // Each warp reduces 2 nodes (8 warps x 2 = 16).
        #pragma unroll
        for (int s = 0; s < 2; s++) {
            int n = wid * 2 + s;
            float p = 0.0f;
            #pragma unroll
            for (int i = 0; i < 4; i++) {
                int c = lane + i * 32;
                float h = Hs[n * 128 + c] + b1[c];
                p = fmaf(fmaxf(h, 0.0f), W2[c], p);
            }
            #pragma unroll
            for (int off = 16; off > 0; off >>= 1)
                p += __shfl_xor_sync(0xFFFFFFFFu, p, off);
            if (lane == 0) out[n0 + n] = p + b2[0];
        }
        __syncthreads();
    }
}

// ---------------------------------------------------------------------------
extern "C" void kernel_launch(void* const* d_in, const int* in_sizes, int n_in,
                              void* d_out, int out_size) {
    const float* user_x  = (const float*)d_in[0];
    const float* movie_x = (const float*)d_in[1];
    const int*   ei      = (const int*)d_in[2];   // int32 (JAX x64 disabled)
    const float* ea      = (const float*)d_in[3];
    const float* W_user  = (const float*)d_in[4];
    const float* b_user  = (const float*)d_in[5];
    const float* W_movie = (const float*)d_in[6];
    const float* b_movie = (const float*)d_in[7];
    const float* W1      = (const float*)d_in[8];
    const float* b1      = (const float*)d_in[9];
    const float* W2      = (const float*)d_in[10];
    const float* b2      = (const float*)d_in[11];
    float* out = (float*)d_out;

    static int smem_set = 0;
    const int mlp_smem = (128 * 128 + 16 * A_LD + 16 * 128) * sizeof(float);
    if (!smem_set) {
        cudaFuncSetAttribute(k_mlp, cudaFuncAttributeMaxDynamicSharedMemorySize, mlp_smem);
        smem_set = 1;
    }

    k_deg_init<<<(N_NODES + 255) / 256, 256>>>();
    k_deg_accum<<<(N_EDGES + 255) / 256, 256>>>(ei, ea);
    k_dinv<<<(N_NODES + 255) / 256, 256>>>();
    k_xw<<<N_NODES / 8, 128>>>(user_x, movie_x, W_user, b_user, W_movie, b_movie);
    k_scatter<<<N_EDGES / 8, 256>>>(ei, ea);
    k_mlp<<<MLP_BLOCKS, 256, mlp_smem>>>(W1, b1, W2, b2, out);
}

// round 8
// speedup vs baseline: 1.3523x; 1.3523x over previous
#include <cuda_runtime.h>
#include <cuda_bf16.h>
#include <math.h>

#define N_NODES 100000
#define N_EDGES 1000000
#define FULL 0xFFFFFFFFu

// Scratch (device globals — no dynamic allocation allowed)
__device__ __align__(16) float g_dinv[N_NODES];
__device__ __align__(16) float g_xw[(size_t)N_NODES * 128];
__device__ __align__(16) float g_agg[(size_t)N_NODES * 128];
// CSR by destination (col)
__device__ int   g_cnt[N_NODES];        // in-degree (edge count)
__device__ int   g_off[N_NODES];        // exclusive prefix of g_cnt
__device__ int   g_cur[N_NODES];        // running fill cursor
__device__ int   g_bsum[128];           // block sums for scan
__device__ int   g_src[N_EDGES];        // source node per CSR slot
__device__ float g_ewc[N_EDGES];        // edge weight per CSR slot

// ---------------------------------------------------------------------------
__global__ void k_zero() {
    int i = blockIdx.x * blockDim.x + threadIdx.x;
    if (i < N_NODES) g_cnt[i] = 0;
}

__global__ void k_hist(const int* __restrict__ ei) {
    int e = blockIdx.x * blockDim.x + threadIdx.x;
    if (e < N_EDGES) atomicAdd(&g_cnt[ei[N_EDGES + e]], 1);
}

// Scan phase 1: per-block (1024) exclusive scan of g_cnt -> g_off, block total -> g_bsum
__global__ void __launch_bounds__(1024) k_scan1() {
    __shared__ int wsum[32];
    int i = blockIdx.x * 1024 + threadIdx.x;
    int lane = threadIdx.x & 31, wid = threadIdx.x >> 5;
    int c = (i < N_NODES) ? g_cnt[i] : 0;
    int v = c;
    #pragma unroll
    for (int o = 1; o < 32; o <<= 1) {
        int t = __shfl_up_sync(FULL, v, o);
        if (lane >= o) v += t;
    }
    if (lane == 31) wsum[wid] = v;
    __syncthreads();
    if (wid == 0) {
        int s = wsum[lane];
        #pragma unroll
        for (int o = 1; o < 32; o <<= 1) {
            int t = __shfl_up_sync(FULL, s, o);
            if (lane >= o) s += t;
        }
        wsum[lane] = s;
    }
    __syncthreads();
    int base = (wid > 0) ? wsum[wid - 1] : 0;
    int incl = v + base;
    if (i < N_NODES) g_off[i] = incl - c;
    if (threadIdx.x == 1023) g_bsum[blockIdx.x] = incl;
}

// Scan phase 2: serial exclusive scan of block sums (98 values — trivial)
__global__ void k_scan2(int nb) {
    if (threadIdx.x == 0 && blockIdx.x == 0) {
        int s = 0;
        for (int b = 0; b < nb; b++) { int t = g_bsum[b]; g_bsum[b] = s; s += t; }
    }
}

// Scan phase 3: add block base; init cursor
__global__ void k_scan3() {
    int i = blockIdx.x * blockDim.x + threadIdx.x;
    if (i < N_NODES) {
        int o = g_off[i] + g_bsum[i >> 10];
        g_off[i] = o;
        g_cur[i] = o;
    }
}

// Fill CSR: slot = cursor++, store src row + edge weight
__global__ void k_csr(const int* __restrict__ ei, const float* __restrict__ ew) {
    int e = blockIdx.x * blockDim.x + threadIdx.x;
    if (e < N_EDGES) {
        int col = ei[N_EDGES + e];
        int pos = atomicAdd(&g_cur[col], 1);
        g_src[pos] = ei[e];
        g_ewc[pos] = ew[e];
    }
}

// Weighted degree (self-loop w=1 + sum of incoming ew) -> dinv
__global__ void k_degdinv() {
    int i = blockIdx.x * blockDim.x + threadIdx.x;
    if (i < N_NODES) {
        float s = 1.0f;
        int o = g_off[i], c = g_cnt[i];
        for (int k = 0; k < c; k++) s += g_ewc[o + k];
        g_dinv[i] = rsqrtf(s);
    }
}

// xw = x@W (both convs). 8 nodes per 128-thread block.
__global__ void __launch_bounds__(128) k_xw(
    const float* __restrict__ user_x, const float* __restrict__ movie_x,
    const float* __restrict__ Wu, const float* __restrict__ Wm)
{
    int nb = blockIdx.x * 8;
    int j  = threadIdx.x;
    __shared__ float su[8 * 3];
    __shared__ float sv[8 * 18];

    if (j < 24) su[j] = user_x[(size_t)nb * 3 + j];
    for (int i = j; i < 144; i += 128) sv[i] = movie_x[(size_t)nb * 18 + i];

    float w[18];
    if (j < 64) {
        #pragma unroll
        for (int k = 0; k < 3; k++) w[k] = Wu[k * 64 + j];
    } else {
        int jj = j - 64;
        #pragma unroll
        for (int k = 0; k < 18; k++) w[k] = Wm[k * 64 + jj];
    }
    __syncthreads();

    #pragma unroll
    for (int nd = 0; nd < 8; nd++) {
        float acc = 0.0f;
        if (j < 64) {
            #pragma unroll
            for (int k = 0; k < 3; k++) acc = fmaf(su[nd * 3 + k], w[k], acc);
        } else {
            #pragma unroll
            for (int k = 0; k < 18; k++) acc = fmaf(sv[nd * 18 + k], w[k], acc);
        }
        g_xw[(size_t)(nb + nd) * 128 + j] = acc;
    }
}

// Aggregate: one warp per destination node, register accumulation, no atomics.
__global__ void __launch_bounds__(256) k_agg(
    const float* __restrict__ bu, const float* __restrict__ bm)
{
    int node = (blockIdx.x * blockDim.x + threadIdx.x) >> 5;
    int lane = threadIdx.x & 31;
    if (node >= N_NODES) return;

    int off = g_off[node], cnt = g_cnt[node];
    float dc = g_dinv[node];

    // self-loop term + bias
    float4 acc = reinterpret_cast<const float4*>(g_xw + (size_t)node * 128)[lane];
    float s2 = dc * dc;
    float4 bias = (lane < 16) ? reinterpret_cast<const float4*>(bu)[lane]
                              : reinterpret_cast<const float4*>(bm)[lane - 16];
    acc.x = fmaf(acc.x, s2, bias.x);
    acc.y = fmaf(acc.y, s2, bias.y);
    acc.z = fmaf(acc.z, s2, bias.z);
    acc.w = fmaf(acc.w, s2, bias.w);

    for (int base = 0; base < cnt; base += 32) {
        int rem = min(cnt - base, 32);
        int src = 0; float nrm = 0.0f;
        if (lane < rem) {
            int idx = off + base + lane;
            src = g_src[idx];
            nrm = g_dinv[src] * g_ewc[idx] * dc;
        }
        int j = 0;
        for (; j + 4 <= rem; j += 4) {
            int s0 = __shfl_sync(FULL, src, j);
            int s1 = __shfl_sync(FULL, src, j + 1);
            int s2i = __shfl_sync(FULL, src, j + 2);
            int s3 = __shfl_sync(FULL, src, j + 3);
            float n0 = __shfl_sync(FULL, nrm, j);
            float n1 = __shfl_sync(FULL, nrm, j + 1);
            float n2 = __shfl_sync(FULL, nrm, j + 2);
            float n3 = __shfl_sync(FULL, nrm, j + 3);
            float4 v0 = reinterpret_cast<const float4*>(g_xw + (size_t)s0 * 128)[lane];
            float4 v1 = reinterpret_cast<const float4*>(g_xw + (size_t)s1 * 128)[lane];
            float4 v2 = reinterpret_cast<const float4*>(g_xw + (size_t)s2i * 128)[lane];
            float4 v3 = reinterpret_cast<const float4*>(g_xw + (size_t)s3 * 128)[lane];
            acc.x = fmaf(n0, v0.x, acc.x); acc.y = fmaf(n0, v0.y, acc.y);
            acc.z = fmaf(n0, v0.z, acc.z); acc.w = fmaf(n0, v0.w, acc.w);
            acc.x = fmaf(n1, v1.x, acc.x); acc.y = fmaf(n1, v1.y, acc.y);
            acc.z = fmaf(n1, v1.z, acc.z); acc.w = fmaf(n1, v1.w, acc.w);
            acc.x = fmaf(n2, v2.x, acc.x); acc.y = fmaf(n2, v2.y, acc.y);
            acc.z = fmaf(n2, v2.z, acc.z); acc.w = fmaf(n2, v2.w, acc.w);
            acc.x = fmaf(n3, v3.x, acc.x); acc.y = fmaf(n3, v3.y, acc.y);
            acc.z = fmaf(n3, v3.z, acc.z); acc.w = fmaf(n3, v3.w, acc.w);
        }
        for (; j < rem; j++) {
            int s = __shfl_sync(FULL, src, j);
            float n = __shfl_sync(FULL, nrm, j);
            float4 v = reinterpret_cast<const float4*>(g_xw + (size_t)s * 128)[lane];
            acc.x = fmaf(n, v.x, acc.x); acc.y = fmaf(n, v.y, acc.y);
            acc.z = fmaf(n, v.z, acc.z); acc.w = fmaf(n, v.w, acc.w);
        }
    }
    reinterpret_cast<float4*>(g_agg + (size_t)node * 128)[lane] = acc;
}

// MLP head (round-5 FFMA version, known-good)
__global__ void __launch_bounds__(128) k_mlp(
    const float* __restrict__ W1, const float* __restrict__ b1,
    const float* __restrict__ W2, const float* __restrict__ b2,
    float* __restrict__ out)
{
    __shared__ float v[4][128];
    __shared__ float hsum[4][4];
    int j = threadIdx.x;
    int warp = j >> 5, lane = j & 31;
    float w2j = W2[j];
    float b1j = b1[j];
    float b2v = b2[0];

    for (int n0 = blockIdx.x * 4; n0 < N_NODES; n0 += gridDim.x * 4) {
        #pragma unroll
        for (int nd = 0; nd < 4; nd++)
            v[nd][j] = g_agg[(size_t)(n0 + nd) * 128 + j];
        __syncthreads();

        float a0 = b1j, a1 = b1j, a2 = b1j, a3 = b1j;
        #pragma unroll 8
        for (int k = 0; k < 128; k++) {
            float w = W1[k * 128 + j];
            a0 = fmaf(v[0][k], w, a0);
            a1 = fmaf(v[1][k], w, a1);
            a2 = fmaf(v[2][k], w, a2);
            a3 = fmaf(v[3][k], w, a3);
        }
        float p0 = fmaxf(a0, 0.0f) * w2j;
        float p1 = fmaxf(a1, 0.0f) * w2j;
        float p2 = fmaxf(a2, 0.0f) * w2j;
        float p3 = fmaxf(a3, 0.0f) * w2j;
        #pragma unroll
        for (int off = 16; off > 0; off >>= 1) {
            p0 += __shfl_xor_sync(FULL, p0, off);
            p1 += __shfl_xor_sync(FULL, p1, off);
            p2 += __shfl_xor_sync(FULL, p2, off);
            p3 += __shfl_xor_sync(FULL, p3, off);
        }
        if (lane == 0) {
            hsum[0][warp] = p0; hsum[1][warp] = p1;
            hsum[2][warp] = p2; hsum[3][warp] = p3;
        }
        __syncthreads();
        if (j < 4) {
            out[n0 + j] = hsum[j][0] + hsum[j][1] + hsum[j][2] + hsum[j][3] + b2v;
        }
        __syncthreads();
    }
}

// ---------------------------------------------------------------------------
extern "C" void kernel_launch(void* const* d_in, const int* in_sizes, int n_in,
                              void* d_out, int out_size) {
    const float* user_x  = (const float*)d_in[0];
    const float* movie_x = (const float*)d_in[1];
    const int*   ei      = (const int*)d_in[2];   // int32 (JAX x64 disabled)
    const float* ea      = (const float*)d_in[3];
    const float* W_user  = (const float*)d_in[4];
    const float* b_user  = (const float*)d_in[5];
    const float* W_movie = (const float*)d_in[6];
    const float* b_movie = (const float*)d_in[7];
    const float* W1      = (const float*)d_in[8];
    const float* b1      = (const float*)d_in[9];
    const float* W2      = (const float*)d_in[10];
    const float* b2      = (const float*)d_in[11];
    float* out = (float*)d_out;

    const int nb_scan = (N_NODES + 1023) / 1024;  // 98

    k_zero   <<<(N_NODES + 255) / 256, 256>>>();
    k_hist   <<<(N_EDGES + 255) / 256, 256>>>(ei);
    k_scan1  <<<nb_scan, 1024>>>();
    k_scan2  <<<1, 32>>>(nb_scan);
    k_scan3  <<<(N_NODES + 255) / 256, 256>>>();
    k_csr    <<<(N_EDGES + 255) / 256, 256>>>(ei, ea);
    k_degdinv<<<(N_NODES + 255) / 256, 256>>>();
    k_xw     <<<N_NODES / 8, 128>>>(user_x, movie_x, W_user, W_movie);
    k_agg    <<<(N_NODES * 32 + 255) / 256, 256>>>(b_user, b_movie);
    k_mlp    <<<N_NODES / 4, 128>>>(W1, b1, W2, b2, out);
}

// round 9
// speedup vs baseline: 1.6805x; 1.2426x over previous
#include <cuda_runtime.h>
#include <cuda_bf16.h>
#include <mma.h>
#include <math.h>

using namespace nvcuda;

#define N_NODES 100000
#define N_PAD   100096                 // 782 * 128
#define N_EDGES 1000000
#define FULL 0xFFFFFFFFu

// Scratch (device globals — no dynamic allocation allowed)
__device__ __align__(16) float g_dinv[N_NODES];
__device__ __align__(16) float g_xw[(size_t)N_NODES * 128];
__device__ __align__(16) float g_agg[(size_t)N_PAD * 128];   // pad rows stay 0
// CSR by destination (col)
__device__ int   g_cnt[N_NODES];
__device__ int   g_off[N_NODES];
__device__ int   g_cur[N_NODES];
__device__ int   g_bsum[128];
__device__ int   g_src[N_EDGES];
__device__ float g_ewc[N_EDGES];

// ---------------------------------------------------------------------------
__global__ void k_zero() {
    int i = blockIdx.x * blockDim.x + threadIdx.x;
    if (i < N_NODES) g_cnt[i] = 0;
}

__global__ void k_hist(const int* __restrict__ ei) {
    int e = blockIdx.x * blockDim.x + threadIdx.x;
    if (e < N_EDGES) atomicAdd(&g_cnt[ei[N_EDGES + e]], 1);
}

// Scan phase 1: per-block (1024) exclusive scan of g_cnt -> g_off, totals -> g_bsum
__global__ void __launch_bounds__(1024) k_scan1() {
    __shared__ int wsum[32];
    int i = blockIdx.x * 1024 + threadIdx.x;
    int lane = threadIdx.x & 31, wid = threadIdx.x >> 5;
    int c = (i < N_NODES) ? g_cnt[i] : 0;
    int v = c;
    #pragma unroll
    for (int o = 1; o < 32; o <<= 1) {
        int t = __shfl_up_sync(FULL, v, o);
        if (lane >= o) v += t;
    }
    if (lane == 31) wsum[wid] = v;
    __syncthreads();
    if (wid == 0) {
        int s = wsum[lane];
        #pragma unroll
        for (int o = 1; o < 32; o <<= 1) {
            int t = __shfl_up_sync(FULL, s, o);
            if (lane >= o) s += t;
        }
        wsum[lane] = s;
    }
    __syncthreads();
    int base = (wid > 0) ? wsum[wid - 1] : 0;
    int incl = v + base;
    if (i < N_NODES) g_off[i] = incl - c;
    if (threadIdx.x == 1023) g_bsum[blockIdx.x] = incl;
}

// Scan phase 2: parallel exclusive scan of 98 block sums (one 128-thread block)
__global__ void __launch_bounds__(128) k_scan2(int nb) {
    __shared__ int ws[4];
    int t = threadIdx.x, lane = t & 31, w = t >> 5;
    int c = (t < nb) ? g_bsum[t] : 0;
    int v = c;
    #pragma unroll
    for (int o = 1; o < 32; o <<= 1) {
        int x = __shfl_up_sync(FULL, v, o);
        if (lane >= o) v += x;
    }
    if (lane == 31) ws[w] = v;
    __syncthreads();
    int base = 0;
    #pragma unroll
    for (int k = 0; k < 4; k++) if (k < w) base += ws[k];
    if (t < nb) g_bsum[t] = v + base - c;   // exclusive
}

// Scan phase 3: add block base; init cursor
__global__ void k_scan3() {
    int i = blockIdx.x * blockDim.x + threadIdx.x;
    if (i < N_NODES) {
        int o = g_off[i] + g_bsum[i >> 10];
        g_off[i] = o;
        g_cur[i] = o;
    }
}

// Fill CSR
__global__ void k_csr(const int* __restrict__ ei, const float* __restrict__ ew) {
    int e = blockIdx.x * blockDim.x + threadIdx.x;
    if (e < N_EDGES) {
        int col = ei[N_EDGES + e];
        int pos = atomicAdd(&g_cur[col], 1);
        g_src[pos] = ei[e];
        g_ewc[pos] = ew[e];
    }
}

// Weighted degree -> dinv
__global__ void k_degdinv() {
    int i = blockIdx.x * blockDim.x + threadIdx.x;
    if (i < N_NODES) {
        float s = 1.0f;
        int o = g_off[i], c = g_cnt[i];
        for (int k = 0; k < c; k++) s += g_ewc[o + k];
        g_dinv[i] = rsqrtf(s);
    }
}

// xw = x@W (both convs). 8 nodes per 128-thread block.
__global__ void __launch_bounds__(128) k_xw(
    const float* __restrict__ user_x, const float* __restrict__ movie_x,
    const float* __restrict__ Wu, const float* __restrict__ Wm)
{
    int nb = blockIdx.x * 8;
    int j  = threadIdx.x;
    __shared__ float su[8 * 3];
    __shared__ float sv[8 * 18];

    if (j < 24) su[j] = user_x[(size_t)nb * 3 + j];
    for (int i = j; i < 144; i += 128) sv[i] = movie_x[(size_t)nb * 18 + i];

    float w[18];
    if (j < 64) {
        #pragma unroll
        for (int k = 0; k < 3; k++) w[k] = Wu[k * 64 + j];
    } else {
        int jj = j - 64;
        #pragma unroll
        for (int k = 0; k < 18; k++) w[k] = Wm[k * 64 + jj];
    }
    __syncthreads();

    #pragma unroll
    for (int nd = 0; nd < 8; nd++) {
        float acc = 0.0f;
        if (j < 64) {
            #pragma unroll
            for (int k = 0; k < 3; k++) acc = fmaf(su[nd * 3 + k], w[k], acc);
        } else {
            #pragma unroll
            for (int k = 0; k < 18; k++) acc = fmaf(sv[nd * 18 + k], w[k], acc);
        }
        g_xw[(size_t)(nb + nd) * 128 + j] = acc;
    }
}

// Aggregate: one warp per destination node, register accumulation, no atomics.
__global__ void __launch_bounds__(256) k_agg(
    const float* __restrict__ bu, const float* __restrict__ bm)
{
    int node = (blockIdx.x * blockDim.x + threadIdx.x) >> 5;
    int lane = threadIdx.x & 31;
    if (node >= N_NODES) return;

    int off = g_off[node], cnt = g_cnt[node];
    float dc = g_dinv[node];

    float4 acc = reinterpret_cast<const float4*>(g_xw + (size_t)node * 128)[lane];
    float s2 = dc * dc;
    float4 bias = (lane < 16) ? reinterpret_cast<const float4*>(bu)[lane]
                              : reinterpret_cast<const float4*>(bm)[lane - 16];
    acc.x = fmaf(acc.x, s2, bias.x);
    acc.y = fmaf(acc.y, s2, bias.y);
    acc.z = fmaf(acc.z, s2, bias.z);
    acc.w = fmaf(acc.w, s2, bias.w);

    for (int base = 0; base < cnt; base += 32) {
        int rem = min(cnt - base, 32);
        int src = 0; float nrm = 0.0f;
        if (lane < rem) {
            int idx = off + base + lane;
            src = g_src[idx];
            nrm = g_dinv[src] * g_ewc[idx] * dc;
        }
        int j = 0;
        for (; j + 4 <= rem; j += 4) {
            int s0 = __shfl_sync(FULL, src, j);
            int s1 = __shfl_sync(FULL, src, j + 1);
            int s2i = __shfl_sync(FULL, src, j + 2);
            int s3 = __shfl_sync(FULL, src, j + 3);
            float n0 = __shfl_sync(FULL, nrm, j);
            float n1 = __shfl_sync(FULL, nrm, j + 1);
            float n2 = __shfl_sync(FULL, nrm, j + 2);
            float n3 = __shfl_sync(FULL, nrm, j + 3);
            float4 v0 = reinterpret_cast<const float4*>(g_xw + (size_t)s0 * 128)[lane];
            float4 v1 = reinterpret_cast<const float4*>(g_xw + (size_t)s1 * 128)[lane];
            float4 v2 = reinterpret_cast<const float4*>(g_xw + (size_t)s2i * 128)[lane];
            float4 v3 = reinterpret_cast<const float4*>(g_xw + (size_t)s3 * 128)[lane];
            acc.x = fmaf(n0, v0.x, acc.x); acc.y = fmaf(n0, v0.y, acc.y);
            acc.z = fmaf(n0, v0.z, acc.z); acc.w = fmaf(n0, v0.w, acc.w);
            acc.x = fmaf(n1, v1.x, acc.x); acc.y = fmaf(n1, v1.y, acc.y);
            acc.z = fmaf(n1, v1.z, acc.z); acc.w = fmaf(n1, v1.w, acc.w);
            acc.x = fmaf(n2, v2.x, acc.x); acc.y = fmaf(n2, v2.y, acc.y);
            acc.z = fmaf(n2, v2.z, acc.z); acc.w = fmaf(n2, v2.w, acc.w);
            acc.x = fmaf(n3, v3.x, acc.x); acc.y = fmaf(n3, v3.y, acc.y);
            acc.z = fmaf(n3, v3.z, acc.z); acc.w = fmaf(n3, v3.w, acc.w);
        }
        for (; j < rem; j++) {
            int s = __shfl_sync(FULL, src, j);
            float n = __shfl_sync(FULL, nrm, j);
            float4 v = reinterpret_cast<const float4*>(g_xw + (size_t)s * 128)[lane];
            acc.x = fmaf(n, v.x, acc.x); acc.y = fmaf(n, v.y, acc.y);
            acc.z = fmaf(n, v.z, acc.z); acc.w = fmaf(n, v.w, acc.w);
        }
    }
    reinterpret_cast<float4*>(g_agg + (size_t)node * 128)[lane] = acc;
}

// ---------------------------------------------------------------------------
// MLP via 3xBF16 tensor cores. Block tile: 128 nodes x 128 channels, K=128.
// 8 warps (2 x 4): warp tile 64 rows x 32 cols = 4x2 16x16 frags.
// hi/lo bf16 split computed ONCE during smem staging; k-loop is pure mma.
// acc += aHi*bHi + aHi*bLo + aLo*bHi   (error ~2^-16 per product)

#define MLD 136   // smem leading dim (elements), mult of 8

extern __shared__ char s_mlp_raw[];

__global__ void __launch_bounds__(256) k_mlp_tc(
    const float* __restrict__ W1, const float* __restrict__ b1,
    const float* __restrict__ W2, const float* __restrict__ b2,
    float* __restrict__ out)
{
    __nv_bfloat16* aHi = reinterpret_cast<__nv_bfloat16*>(s_mlp_raw);
    __nv_bfloat16* aLo = aHi + 128 * MLD;
    __nv_bfloat16* bHi = reinterpret_cast<__nv_bfloat16*>(s_mlp_raw + 2 * 128 * MLD * 2);
    __nv_bfloat16* bLo = bHi + 128 * MLD;
    float* H = reinterpret_cast<float*>(s_mlp_raw);   // reuses A region after k-loop

    int tid  = threadIdx.x;
    int warp = tid >> 5;
    int wm   = warp >> 2;     // 0..1  -> 64-row band
    int wn   = warp & 3;      // 0..3  -> 32-col band
    int n0   = blockIdx.x * 128;

    // Stage A (g_agg rows n0..n0+127) and B (W1, 128x128) with bf16 hi/lo split
    const float4* A4 = reinterpret_cast<const float4*>(g_agg + (size_t)n0 * 128);
    const float4* B4 = reinterpret_cast<const float4*>(W1);
    for (int i = tid; i < 128 * 32; i += 256) {
        int r = i >> 5, c4 = (i & 31) * 4;
        float4 va = A4[i];
        float4 vb = B4[i];
        int o = r * MLD + c4;
        float f;
        __nv_bfloat16 h;
        f = va.x; h = __float2bfloat16_rn(f); aHi[o+0] = h; aLo[o+0] = __float2bfloat16_rn(f - __bfloat162float(h));
        f = va.y; h = __float2bfloat16_rn(f); aHi[o+1] = h; aLo[o+1] = __float2bfloat16_rn(f - __bfloat162float(h));
        f = va.z; h = __float2bfloat16_rn(f); aHi[o+2] = h; aLo[o+2] = __float2bfloat16_rn(f - __bfloat162float(h));
        f = va.w; h = __float2bfloat16_rn(f); aHi[o+3] = h; aLo[o+3] = __float2bfloat16_rn(f - __bfloat162float(h));
        f = vb.x; h = __float2bfloat16_rn(f); bHi[o+0] = h; bLo[o+0] = __float2bfloat16_rn(f - __bfloat162float(h));
        f = vb.y; h = __float2bfloat16_rn(f); bHi[o+1] = h; bLo[o+1] = __float2bfloat16_rn(f - __bfloat162float(h));
        f = vb.z; h = __float2bfloat16_rn(f); bHi[o+2] = h; bLo[o+2] = __float2bfloat16_rn(f - __bfloat162float(h));
        f = vb.w; h = __float2bfloat16_rn(f); bHi[o+3] = h; bLo[o+3] = __float2bfloat16_rn(f - __bfloat162float(h));
    }
    __syncthreads();

    wmma::fragment<wmma::accumulator, 16, 16, 16, float> acc[4][2];
    #pragma unroll
    for (int fm = 0; fm < 4; fm++)
        #pragma unroll
        for (int fn = 0; fn < 2; fn++)
            wmma::fill_fragment(acc[fm][fn], 0.0f);

    #pragma unroll
    for (int k0 = 0; k0 < 128; k0 += 16) {
        wmma::fragment<wmma::matrix_a, 16, 16, 16, __nv_bfloat16, wmma::row_major> ah[4], al[4];
        wmma::fragment<wmma::matrix_b, 16, 16, 16, __nv_bfloat16, wmma::row_major> bh[2], bl[2];
        #pragma unroll
        for (int fm = 0; fm < 4; fm++) {
            int ro = (wm * 64 + fm * 16) * MLD + k0;
            wmma::load_matrix_sync(ah[fm], aHi + ro, MLD);
            wmma::load_matrix_sync(al[fm], aLo + ro, MLD);
        }
        #pragma unroll
        for (int fn = 0; fn < 2; fn++) {
            int co = k0 * MLD + wn * 32 + fn * 16;
            wmma::load_matrix_sync(bh[fn], bHi + co, MLD);
            wmma::load_matrix_sync(bl[fn], bLo + co, MLD);
        }
        #pragma unroll
        for (int fm = 0; fm < 4; fm++)
            #pragma unroll
            for (int fn = 0; fn < 2; fn++) {
                wmma::mma_sync(acc[fm][fn], ah[fm], bl[fn], acc[fm][fn]);
                wmma::mma_sync(acc[fm][fn], al[fm], bh[fn], acc[fm][fn]);
                wmma::mma_sync(acc[fm][fn], ah[fm], bh[fn], acc[fm][fn]);
            }
    }
    __syncthreads();   // all warps done reading A before H overwrites it

    #pragma unroll
    for (int fm = 0; fm < 4; fm++)
        #pragma unroll
        for (int fn = 0; fn < 2; fn++)
            wmma::store_matrix_sync(H + (wm * 64 + fm * 16) * MLD + wn * 32 + fn * 16,
                                    acc[fm][fn], MLD, wmma::mem_row_major);
    __syncthreads();

    // Epilogue: out[n] = sum_c relu(H[n][c] + b1[c]) * W2[c] + b2
    if (tid < 128) {
        int node = n0 + tid;
        if (node < N_NODES) {
            float p = 0.0f;
            #pragma unroll 8
            for (int c = 0; c < 128; c++) {
                float h = H[tid * MLD + c] + b1[c];
                p = fmaf(fmaxf(h, 0.0f), W2[c], p);
            }
            out[node] = p + b2[0];
        }
    }
}

// ---------------------------------------------------------------------------
extern "C" void kernel_launch(void* const* d_in, const int* in_sizes, int n_in,
                              void* d_out, int out_size) {
    const float* user_x  = (const float*)d_in[0];
    const float* movie_x = (const float*)d_in[1];
    const int*   ei      = (const int*)d_in[2];   // int32 (JAX x64 disabled)
    const float* ea      = (const float*)d_in[3];
    const float* W_user  = (const float*)d_in[4];
    const float* b_user  = (const float*)d_in[5];
    const float* W_movie = (const float*)d_in[6];
    const float* b_movie = (const float*)d_in[7];
    const float* W1      = (const float*)d_in[8];
    const float* b1      = (const float*)d_in[9];
    const float* W2      = (const float*)d_in[10];
    const float* b2      = (const float*)d_in[11];
    float* out = (float*)d_out;

    const int nb_scan = (N_NODES + 1023) / 1024;  // 98
    const int mlp_smem = 4 * 128 * MLD * 2;       // 139,264 B

    static int smem_set = 0;
    if (!smem_set) {
        cudaFuncSetAttribute(k_mlp_tc, cudaFuncAttributeMaxDynamicSharedMemorySize, mlp_smem);
        smem_set = 1;
    }

    k_zero   <<<(N_NODES + 255) / 256, 256>>>();
    k_hist   <<<(N_EDGES + 255) / 256, 256>>>(ei);
    k_scan1  <<<nb_scan, 1024>>>();
    k_scan2  <<<1, 128>>>(nb_scan);
    k_scan3  <<<(N_NODES + 255) / 256, 256>>>();
    k_csr    <<<(N_EDGES + 255) / 256, 256>>>(ei, ea);
    k_degdinv<<<(N_NODES + 255) / 256, 256>>>();
    k_xw     <<<N_NODES / 8, 128>>>(user_x, movie_x, W_user, W_movie);
    k_agg    <<<(N_NODES * 32 + 255) / 256, 256>>>(b_user, b_movie);
    k_mlp_tc <<<N_PAD / 128, 256, mlp_smem>>>(W1, b1, W2, b2, out);
}